// round 10
// baseline (speedup 1.0000x reference)
#include <cuda_runtime.h>
#include <math.h>
#include <stdint.h>

#define SEQ 1024
#define BB  64
#define DD  512
#define HH  512
#define BH  (BB * HH)

#define NCTA0 64   // layer-0 CTAs, 8 cols each
#define NCTA1 64   // layer-1 CTAs, 8 cols each
#define NTHR  256

typedef unsigned long long u64;

// Scratch (allocation-free rule: __device__ globals)
__device__ float g_z0[SEQ * BB * HH];   // x@Wx0 + bx0 + bh0 (b-major)
__device__ float g_h0[SEQ * BB * HH];   // layer-0 hidden history (b-major)
__device__ int   g_flag0[SEQ];
__device__ int   g_flag1[SEQ];

// ---------------------------------------------------------------- helpers
__device__ __forceinline__ int ld_acq(const int* p) {
    int v;
    asm volatile("ld.acquire.gpu.s32 %0, [%1];" : "=r"(v) : "l"(p) : "memory");
    return v;
}
__device__ __forceinline__ void red_release(int* p) {
    asm volatile("red.release.gpu.global.add.s32 [%0], 1;" :: "l"(p) : "memory");
}
__device__ __forceinline__ void wait_flag(const int* p, int target) {
    while (ld_acq(p) < target) {}
}
__device__ __forceinline__ u64 dup2(float x) {
    u64 r; asm("mov.b64 %0, {%1, %1};" : "=l"(r) : "f"(x)); return r;
}
__device__ __forceinline__ void fma2(u64& acc, u64 a, u64 b) {
    asm("fma.rn.f32x2 %0, %1, %2, %0;" : "+l"(acc) : "l"(a), "l"(b));
}
__device__ __forceinline__ float2 unp2(u64 v) {
    float2 f; asm("mov.b64 {%0, %1}, %2;" : "=f"(f.x), "=f"(f.y) : "l"(v)); return f;
}
__device__ __forceinline__ float fold2(u64 v) {
    float2 f = unp2(v); return f.x + f.y;
}
__device__ __forceinline__ void cp16(uint32_t s, const void* g) {
    asm volatile("cp.async.cg.shared.global [%0], [%1], 16;" :: "r"(s), "l"(g));
}
__device__ __forceinline__ void cp_commit() {
    asm volatile("cp.async.commit_group;" ::: "memory");
}
#define CP_WAIT(N) asm volatile("cp.async.wait_group %0;" :: "n"(N) : "memory")

#define HS0 516     // L0 h row stride (floats); quad-bank groups balanced
#define HS1 132     // L1 ring-slot row stride (128k chunk + pad)
#define SLOT (64 * HS1)   // 8448 floats per ring slot
#define WS0 516     // L0 wT row stride
#define WS1 1032    // L1 wT row stride (K=1024)
#define RSL 576     // red: floats per k-slice (16 bg * 36)
#define RBG 36      // red: floats per bg (32 + 4 pad)

// Stage one 128-k chunk (64 rows x 128 floats = 32KB). 8 cp16/thread.
// L0 flavor: into flat hs at column c*128.
__device__ __forceinline__ void stage_chunkL0(uint32_t s0, const float* src,
                                              int c, int tid) {
#pragma unroll
    for (int j = 0; j < 8; j++) {
        int id = tid + j * NTHR;            // 0..2047
        int b = id >> 5, kc = id & 31;
        cp16(s0 + (uint32_t)((b * HS0 + c * 128 + kc * 4) * 4),
             src + (size_t)b * HH + c * 128 + kc * 4);
    }
    cp_commit();
}
// L1 flavor: k's [koff, koff+128) into a ring slot.
__device__ __forceinline__ void stage_slot(uint32_t sdst, const float* src,
                                           int koff, int tid) {
#pragma unroll
    for (int j = 0; j < 8; j++) {
        int id = tid + j * NTHR;
        int b = id >> 5, kc = id & 31;
        cp16(sdst + (uint32_t)((b * HS1 + kc * 4) * 4),
             src + (size_t)b * HH + koff + kc * 4);
    }
    cp_commit();
}

// 8-k segment. 4 batches x 8 cols per thread, K-packed f32x2.
template<int WS>
__device__ __forceinline__ void seg8(u64* acc,
                                     const float* hr0, const float* hr1,
                                     const float* hr2, const float* hr3,
                                     const float* wk)
{
#pragma unroll
    for (int i = 0; i < 8; i += 4) {
        ulonglong2 ha = *(const ulonglong2*)(hr0 + i);
        ulonglong2 hb = *(const ulonglong2*)(hr1 + i);
        ulonglong2 hc = *(const ulonglong2*)(hr2 + i);
        ulonglong2 hd = *(const ulonglong2*)(hr3 + i);
#pragma unroll
        for (int c = 0; c < 8; c++) {
            ulonglong2 w = *(const ulonglong2*)(wk + c * WS + i);
            fma2(acc[c],      ha.x, w.x);  fma2(acc[c],      ha.y, w.y);
            fma2(acc[8 + c],  hb.x, w.x);  fma2(acc[8 + c],  hb.y, w.y);
            fma2(acc[16 + c], hc.x, w.x);  fma2(acc[16 + c], hc.y, w.y);
            fma2(acc[24 + c], hd.x, w.x);  fma2(acc[24 + c], hd.y, w.y);
        }
    }
}

// Fold 32 u64 partials to floats and store to red[ks][bg][32] (36-padded).
__device__ __forceinline__ void store_partials(float* redf, const u64* acc,
                                               int ks, int bg) {
    float tmp[32];
#pragma unroll
    for (int j = 0; j < 32; j++) tmp[j] = fold2(acc[j]);
    float* wr = redf + (size_t)ks * RSL + (size_t)bg * RBG;
#pragma unroll
    for (int j = 0; j < 8; j++)
        *(float4*)(wr + 4 * j) = make_float4(tmp[4*j], tmp[4*j+1], tmp[4*j+2], tmp[4*j+3]);
}

// Reduce 16 k-slices for output (b=ob, cols och*4..+3).
__device__ __forceinline__ float4 reduce_outputs(const float* redf, int ob, int och) {
    const float* rp = redf + (size_t)(ob & 15) * RBG + (size_t)(ob >> 4) * 8 + och * 4;
    float4 s = make_float4(0.f, 0.f, 0.f, 0.f);
#pragma unroll
    for (int ks = 0; ks < 16; ks++) {
        float4 p = *(const float4*)(rp + (size_t)ks * RSL);
        s.x += p.x; s.y += p.y; s.z += p.z; s.w += p.w;
    }
    return s;
}

// ---------------------------------------------------------------------------
// Precompute Z0 = X @ Wx0 + bx0 + bh0 + zero the flags.
// ---------------------------------------------------------------------------
__global__ __launch_bounds__(256) void precompute_z0(
    const float* __restrict__ X,
    const float* __restrict__ W,
    const float* __restrict__ bxv,
    const float* __restrict__ bhv)
{
    __shared__ float As[16][64];
    __shared__ float Bs[16][64];
    const int tid = threadIdx.x;

    if (blockIdx.y == 0 && blockIdx.x < 4) {
        int i = blockIdx.x * 256 + tid;
        g_flag0[i] = 0;
        g_flag1[i] = 0;
    }

    const int tx = tid & 15;
    const int ty = tid >> 4;
    const int m0 = blockIdx.x * 64;
    const int n0 = blockIdx.y * 64;
    const int lm = tid >> 2;
    const int lk = (tid & 3) << 2;
    const int lr = tid >> 4;
    const int lc = (tid & 15) << 2;

    u64 acc[4][2];
#pragma unroll
    for (int i = 0; i < 4; i++) { acc[i][0] = 0ULL; acc[i][1] = 0ULL; }

    for (int kc = 0; kc < DD; kc += 16) {
        float4 a4 = *(const float4*)(X + (size_t)(m0 + lm) * DD + kc + lk);
        float4 b4 = *(const float4*)(W + (size_t)(kc + lr) * HH + n0 + lc);
        As[lk + 0][lm] = a4.x;
        As[lk + 1][lm] = a4.y;
        As[lk + 2][lm] = a4.z;
        As[lk + 3][lm] = a4.w;
        *(float4*)&Bs[lr][lc] = b4;
        __syncthreads();
#pragma unroll
        for (int kk = 0; kk < 16; kk++) {
            float4 av = *(const float4*)&As[kk][ty << 2];
            ulonglong2 bq = *(const ulonglong2*)&Bs[kk][tx << 2];
            u64 d;
            d = dup2(av.x); fma2(acc[0][0], d, bq.x); fma2(acc[0][1], d, bq.y);
            d = dup2(av.y); fma2(acc[1][0], d, bq.x); fma2(acc[1][1], d, bq.y);
            d = dup2(av.z); fma2(acc[2][0], d, bq.x); fma2(acc[2][1], d, bq.y);
            d = dup2(av.w); fma2(acc[3][0], d, bq.x); fma2(acc[3][1], d, bq.y);
        }
        __syncthreads();
    }
    const int n = n0 + (tx << 2);
    float4 bx4 = *(const float4*)(bxv + n);
    float4 bh4 = *(const float4*)(bhv + n);
#pragma unroll
    for (int i = 0; i < 4; i++) {
        int m = m0 + (ty << 2) + i;
        float2 c0 = unp2(acc[i][0]);
        float2 c1 = unp2(acc[i][1]);
        float4 o;
        o.x = c0.x + bx4.x + bh4.x;
        o.y = c0.y + bx4.y + bh4.y;
        o.z = c1.x + bx4.z + bh4.z;
        o.w = c1.y + bx4.w + bh4.w;
        *(float4*)(g_z0 + (size_t)m * HH + n) = o;
    }
}

// ---------------------------------------------------------------------------
// Persistent sequential kernel. 128 CTAs (1/SM), 256 threads (8 warps).
//   blocks [0,64):   layer 0, 8 cols, K=512; 4 x 128k cp.async chunks.
//   blocks [64,128): layer 1, 8 cols, K=1024 concat; B (h0[t]@Wx1) first,
//                    A (h1[t-1]@Wh1) second. 5-slot ring: A chunks staged
//                    with >=3-chunk lead so A never stalls on arrival.
//                    redf aliases dead slots 0-1 after the last seg.
// ---------------------------------------------------------------------------
__global__ __launch_bounds__(NTHR) void rnn_seq(
    const float* __restrict__ h_init,
    const float* __restrict__ Wh0,
    const float* __restrict__ Wx1,
    const float* __restrict__ bx1,
    const float* __restrict__ Wh1,
    const float* __restrict__ bh1,
    float* __restrict__ out)
{
    extern __shared__ float sm[];
    const int tid = threadIdx.x;
    const int bg  = tid & 15;
    const int ks  = tid >> 4;        // 0..15
    const int kio = ks * 8;          // k offset inside a 128-chunk
    const int ob  = tid & 63;
    const int och = (tid >> 6) & 1;

    if (blockIdx.x < NCTA0) {
        // ------------------------- layer 0 -------------------------
        const int n0 = blockIdx.x * 8;
        float* hs   = sm;                       // [64][HS0]
        float* wsT  = sm + 64 * HS0;            // [8][WS0]
        float* redf = wsT + 8 * WS0;            // [16][RSL]
        const uint32_t s0 = (uint32_t)__cvta_generic_to_shared(hs);

        for (int i = tid; i < 1024; i += NTHR) {
            int k = i >> 1, cq = i & 1;
            float4 v = *(const float4*)(Wh0 + (size_t)k * HH + n0 + cq * 4);
            wsT[(cq * 4 + 0) * WS0 + k] = v.x;
            wsT[(cq * 4 + 1) * WS0 + k] = v.y;
            wsT[(cq * 4 + 2) * WS0 + k] = v.z;
            wsT[(cq * 4 + 3) * WS0 + k] = v.w;
        }
        __syncthreads();

        const int bo0 = (bg +  0) * HS0 + kio, bo1 = (bg + 16) * HS0 + kio;
        const int bo2 = (bg + 32) * HS0 + kio, bo3 = (bg + 48) * HS0 + kio;

        for (int t = 0; t < SEQ; t++) {
            const float* zp = g_z0 + (size_t)t * BH + (size_t)ob * HH + n0 + och * 4;
            float4 zv = *(const float4*)zp;

            if (t > 0 && tid == 0) wait_flag(&g_flag0[t - 1], NCTA0);
            __syncthreads();
            const float* hp = (t == 0) ? h_init : (g_h0 + (size_t)(t - 1) * BH);
            stage_chunkL0(s0, hp, 0, tid);
            stage_chunkL0(s0, hp, 1, tid);
            stage_chunkL0(s0, hp, 2, tid);
            stage_chunkL0(s0, hp, 3, tid);

            u64 acc[32];
#pragma unroll
            for (int i = 0; i < 32; i++) acc[i] = 0ULL;

#pragma unroll
            for (int c = 0; c < 4; c++) {
                if (c == 0) { CP_WAIT(3); } else if (c == 1) { CP_WAIT(2); }
                else if (c == 2) { CP_WAIT(1); } else { CP_WAIT(0); }
                __syncthreads();
                const int co = c * 128;
                seg8<WS0>(acc, hs + bo0 + co, hs + bo1 + co,
                          hs + bo2 + co, hs + bo3 + co, wsT + co + kio);
            }

            store_partials(redf, acc, ks, bg);
            __syncthreads();
            if (tid < 128) {
                float4 r = reduce_outputs(redf, ob, och);
                float4 v;
                v.x = tanhf(r.x + zv.x); v.y = tanhf(r.y + zv.y);
                v.z = tanhf(r.z + zv.z); v.w = tanhf(r.w + zv.w);
                *(float4*)(g_h0 + (size_t)t * BH + (size_t)ob * HH + n0 + och * 4) = v;
                if (t == SEQ - 1)
                    *(float4*)(out + (size_t)SEQ * BH + (size_t)ob * HH + n0 + och * 4) = v;
            }
            __syncthreads();
            if (tid == 0) red_release(&g_flag0[t]);
        }
    } else {
        // ------------------------- layer 1 -------------------------
        const int n0 = (blockIdx.x - NCTA0) * 8;
        float* ring = sm;                       // 5 slots x [64][HS1]
        float* wsT  = sm + 5 * SLOT;            // [8][WS1]: 0..511 Wh1, 512..1023 Wx1
        float* redf = sm;                       // aliases slots 0-1 (dead at store time)
        uint32_t sslot[5];
#pragma unroll
        for (int s = 0; s < 5; s++)
            sslot[s] = (uint32_t)__cvta_generic_to_shared(ring + s * SLOT);

        for (int i = tid; i < 1024; i += NTHR) {
            int k = i >> 1, cq = i & 1;
            float4 vh = *(const float4*)(Wh1 + (size_t)k * HH + n0 + cq * 4);
            float4 vx = *(const float4*)(Wx1 + (size_t)k * HH + n0 + cq * 4);
            wsT[(cq * 4 + 0) * WS1 + k] = vh.x;
            wsT[(cq * 4 + 1) * WS1 + k] = vh.y;
            wsT[(cq * 4 + 2) * WS1 + k] = vh.z;
            wsT[(cq * 4 + 3) * WS1 + k] = vh.w;
            wsT[(cq * 4 + 0) * WS1 + 512 + k] = vx.x;
            wsT[(cq * 4 + 1) * WS1 + 512 + k] = vx.y;
            wsT[(cq * 4 + 2) * WS1 + 512 + k] = vx.z;
            wsT[(cq * 4 + 3) * WS1 + 512 + k] = vx.w;
        }
        float4 bias;
        {
            const float* bx = bx1 + n0 + och * 4;
            const float* bh = bh1 + n0 + och * 4;
            bias.x = bx[0] + bh[0]; bias.y = bx[1] + bh[1];
            bias.z = bx[2] + bh[2]; bias.w = bx[3] + bh[3];
        }
        __syncthreads();

        const int bo0 = (bg +  0) * HS1 + kio, bo1 = (bg + 16) * HS1 + kio;
        const int bo2 = (bg + 32) * HS1 + kio, bo3 = (bg + 48) * HS1 + kio;

        for (int t = 0; t < SEQ; t++) {
            // ---- stage B (h0[t]) chunks G0..G3 into slots 0..3 ----
            if (tid == 0) wait_flag(&g_flag0[t], NCTA0);
            __syncthreads();
            const float* h0src = g_h0 + (size_t)t * BH;
            stage_slot(sslot[0], h0src, 0,   tid);   // G0
            stage_slot(sslot[1], h0src, 128, tid);   // G1
            stage_slot(sslot[2], h0src, 256, tid);   // G2
            stage_slot(sslot[3], h0src, 384, tid);   // G3

            const float* h1src = (t == 0) ? (h_init + BH)
                                          : (out + (size_t)(t - 1) * BH);
            u64 acc[32];
#pragma unroll
            for (int i = 0; i < 32; i++) acc[i] = 0ULL;

            // seg B0 (slot0, wT cols 512..639); poll flag1 during it
            CP_WAIT(3); __syncthreads();
            seg8<WS1>(acc, ring + bo0, ring + bo1, ring + bo2, ring + bo3,
                      wsT + 512 + kio);
            if (t > 0 && tid == 0) wait_flag(&g_flag1[t - 1], NCTA1);

            // need G1; committed {0..3} -> WAIT(2). Then stage A0(G4,s4), A1(G5,s0).
            CP_WAIT(2); __syncthreads();
            stage_slot(sslot[4], h1src, 0,   tid);   // G4 = A0
            stage_slot(sslot[0], h1src, 128, tid);   // G5 = A1 (slot0 consumed)
            {   // seg B1 (slot1, cols 640..767)
                const float* sp = ring + 1 * SLOT;
                seg8<WS1>(acc, sp + bo0, sp + bo1, sp + bo2, sp + bo3,
                          wsT + 640 + kio);
            }
            // need G2; outstanding allowed {G3,G4,G5} -> WAIT(3)
            CP_WAIT(3); __syncthreads();
            stage_slot(sslot[1], h1src, 256, tid);   // G6 = A2 (slot1 consumed)
            {   // seg B2 (slot2, cols 768..895)
                const float* sp = ring + 2 * SLOT;
                seg8<WS1>(acc, sp + bo0, sp + bo1, sp + bo2, sp + bo3,
                          wsT + 768 + kio);
            }
            // need G3; allowed {G4,G5,G6} -> WAIT(3)
            CP_WAIT(3); __syncthreads();
            stage_slot(sslot[2], h1src, 384, tid);   // G7 = A3 (slot2 consumed)
            {   // seg B3 (slot3, cols 896..1023)
                const float* sp = ring + 3 * SLOT;
                seg8<WS1>(acc, sp + bo0, sp + bo1, sp + bo2, sp + bo3,
                          wsT + 896 + kio);
            }
            // need G4 (A0); allowed {G5,G6,G7} -> WAIT(3)
            CP_WAIT(3); __syncthreads();
            {   // seg A0 (slot4, Wh1 cols 0..127)
                const float* sp = ring + 4 * SLOT;
                seg8<WS1>(acc, sp + bo0, sp + bo1, sp + bo2, sp + bo3,
                          wsT + kio);
            }
            CP_WAIT(2); __syncthreads();
            {   // seg A1 (slot0, cols 128..255)
                seg8<WS1>(acc, ring + bo0, ring + bo1, ring + bo2, ring + bo3,
                          wsT + 128 + kio);
            }
            CP_WAIT(1); __syncthreads();
            {   // seg A2 (slot1, cols 256..383)
                const float* sp = ring + 1 * SLOT;
                seg8<WS1>(acc, sp + bo0, sp + bo1, sp + bo2, sp + bo3,
                          wsT + 256 + kio);
            }
            CP_WAIT(0); __syncthreads();
            {   // seg A3 (slot2, cols 384..511)
                const float* sp = ring + 2 * SLOT;
                seg8<WS1>(acc, sp + bo0, sp + bo1, sp + bo2, sp + bo3,
                          wsT + 384 + kio);
            }
            __syncthreads();   // all warps past slot0/1 reads before redf alias write

            store_partials(redf, acc, ks, bg);
            __syncthreads();
            if (tid < 128) {
                float4 r = reduce_outputs(redf, ob, och);
                float4 v;
                v.x = tanhf(r.x + bias.x); v.y = tanhf(r.y + bias.y);
                v.z = tanhf(r.z + bias.z); v.w = tanhf(r.w + bias.w);
                *(float4*)(out + (size_t)t * BH + (size_t)ob * HH + n0 + och * 4) = v;
                if (t == SEQ - 1)
                    *(float4*)(out + (size_t)SEQ * BH + BH + (size_t)ob * HH + n0 + och * 4) = v;
            }
            __syncthreads();
            if (tid == 0) red_release(&g_flag1[t]);
        }
    }
}

// L1: (5*8448 + 8*1032)*4 = (42240+8256)*4 = 201984 B (redf aliased in ring)
// L0: (64*516 + 8*516 + 16*576)*4 = 185472 B
#define SMEM_BYTES 201984

extern "C" void kernel_launch(void* const* d_in, const int* in_sizes, int n_in,
                              void* d_out, int out_size)
{
    const float* x   = (const float*)d_in[0];
    const float* h0  = (const float*)d_in[1];
    const float* Wx0 = (const float*)d_in[2];
    const float* bx0 = (const float*)d_in[3];
    const float* Wh0 = (const float*)d_in[4];
    const float* bh0 = (const float*)d_in[5];
    const float* Wx1 = (const float*)d_in[6];
    const float* bx1 = (const float*)d_in[7];
    const float* Wh1 = (const float*)d_in[8];
    const float* bh1 = (const float*)d_in[9];
    float* out = (float*)d_out;
    (void)in_sizes; (void)n_in; (void)out_size;

    dim3 gz((SEQ * BB) / 64, HH / 64);
    precompute_z0<<<gz, 256>>>(x, Wx0, bx0, bh0);

    static int attr_set = 0;
    if (!attr_set) {
        cudaFuncSetAttribute(rnn_seq, cudaFuncAttributeMaxDynamicSharedMemorySize,
                             SMEM_BYTES);
        attr_set = 1;
    }
    rnn_seq<<<NCTA0 + NCTA1, NTHR, SMEM_BYTES>>>(h0, Wh0, Wx1, bx1, Wh1, bh1, out);
}